// round 15
// baseline (speedup 1.0000x reference)
#include <cuda_runtime.h>
#include <cstdint>

// Window attention: B_=4096 windows, N=64 tok, C=256, H=8 heads, D=32. fp32 I/O.
// R10-proven kernels; NEW: 4-chunk window pipeline on 2 streams so the
// latency-bound attention kernel fills the tensor-bound GEMM's idle cycles.
//   s0: r0,t0,b0 -> k1 chunks (QKV gemm) -> k3 chunks (proj gemm)
//   s1: k2 chunks (attention), k2cI after k1cI; k3cI after k2cI.
// (PTX target compute_103: tcgen05 unavailable; legacy mma.sync tf32 path.)

#define NWIN   4096
#define CDIM   256
#define NHEAD  8
#define SCALEF 0.17677669529663687f

#define NCHUNK 4
#define WCH    (NWIN / NCHUNK)              // 1024 windows per chunk (mult of 64)
#define MCH    (WCH * 64 / 128)             // 512 m-tiles per chunk

__device__ float  g_QKV[(size_t)NWIN * 64 * 768];
__device__ float  g_O  [(size_t)NWIN * 64 * 256];
__device__ float  g_Xr [(size_t)NWIN * 64 * 256];
__device__ float  g_WqkvT [768 * 256];
__device__ float  g_WprojT[256 * 256];
__device__ float4 g_BM[8 * 64 * 1024];      // 8 MB: [h][w][wm][nt][gid][tig]

__device__ __forceinline__ float tf32r(float x) {
    float y; asm("cvt.rna.tf32.f32 %0, %1;" : "=f"(y) : "f"(x)); return y;
}
__device__ __forceinline__ uint32_t smem_u32(const void* p) {
    uint32_t a;
    asm("{ .reg .u64 t; cvta.to.shared.u64 t, %1; cvt.u32.u64 %0, t; }" : "=r"(a) : "l"(p));
    return a;
}
__device__ __forceinline__ void cp_async16(uint32_t dst, const void* src) {
    asm volatile("cp.async.cg.shared.global [%0], [%1], 16;" :: "r"(dst), "l"(src));
}
__device__ __forceinline__ void cp_commit() {
    asm volatile("cp.async.commit_group;" ::: "memory");
}
template<int N> __device__ __forceinline__ void cp_wait() {
    asm volatile("cp.async.wait_group %0;" :: "n"(N) : "memory");
}

// m16n8k8 tf32 mma: D += A(16x8,row) * B(8x8,col).
__device__ __forceinline__ void mma_tf32(float* d, const uint32_t* a, const uint32_t* b) {
    asm volatile(
        "mma.sync.aligned.m16n8k8.row.col.f32.tf32.tf32.f32 "
        "{%0,%1,%2,%3}, {%4,%5,%6,%7}, {%8,%9}, {%0,%1,%2,%3};"
        : "+f"(d[0]), "+f"(d[1]), "+f"(d[2]), "+f"(d[3])
        : "r"(a[0]), "r"(a[1]), "r"(a[2]), "r"(a[3]), "r"(b[0]), "r"(b[1]));
}

// ---------------------------------------------------------------------------
// Kernel r0: elementwise tf32 rounding (float4).
// ---------------------------------------------------------------------------
__global__ void round_tf32(const float4* __restrict__ in, float4* __restrict__ out)
{
    int i = blockIdx.x * blockDim.x + threadIdx.x;
    float4 v = in[i];
    v.x = tf32r(v.x); v.y = tf32r(v.y); v.z = tf32r(v.z); v.w = tf32r(v.w);
    out[i] = v;
}

// ---------------------------------------------------------------------------
// Kernel t0: transpose src[256, ncol] -> dst[ncol, 256], tf32-rounded.
// ---------------------------------------------------------------------------
__global__ void transpose_tf32(const float* __restrict__ src, float* __restrict__ dst, int ncol)
{
    __shared__ float tile[32][33];
    const int bx = blockIdx.x, by = blockIdx.y;
    const int tx = threadIdx.x, ty0 = threadIdx.y;
    #pragma unroll
    for (int j = 0; j < 32; j += 8)
        tile[ty0 + j][tx] = src[(size_t)(by * 32 + ty0 + j) * ncol + bx * 32 + tx];
    __syncthreads();
    #pragma unroll
    for (int j = 0; j < 32; j += 8)
        dst[(size_t)(bx * 32 + ty0 + j) * 256 + by * 32 + tx] = tf32r(tile[tx][ty0 + j]);
}

// ---------------------------------------------------------------------------
// Kernel b0: build bias+mask fragment table.
// ---------------------------------------------------------------------------
__global__ void bm_build(const float* __restrict__ mask, const float* __restrict__ bt,
                         float4* __restrict__ out)
{
    const int hw = blockIdx.x;             // 0..511
    const int h = hw >> 6, w = hw & 63;
    const int t = threadIdx.x;             // 256
    const int nt = t >> 5, gid = (t >> 2) & 7, tig = t & 3;
    const float* mrow = mask + (size_t)w * 4096;
    float4* op = out + (size_t)hw * 1024 + nt * 32 + gid * 4 + tig;
    const int c = nt * 8 + tig * 2;
    #pragma unroll
    for (int wm = 0; wm < 4; wm++) {
        const int r0 = wm * 16 + gid, r1 = r0 + 8;
        float4 v;
        v.x = bt[(r0 - c + 63) * 8 + h] + mrow[r0 * 64 + c];
        v.y = bt[(r0 - c + 62) * 8 + h] + mrow[r0 * 64 + c + 1];
        v.z = bt[(r1 - c + 63) * 8 + h] + mrow[r1 * 64 + c];
        v.w = bt[(r1 - c + 62) * 8 + h] + mrow[r1 * 64 + c + 1];
        op[wm * 256] = v;
    }
}

// ---------------------------------------------------------------------------
// Kernel k1/k3: 3-stage cp.async mma.sync tf32 GEMM (R10-proven version).
// ---------------------------------------------------------------------------
#define BM 128
#define BK 32
#define KP 36
#define STG (BM * KP)
#define NST 3
#define GEMM_SMEM (2 * NST * STG * 4)       // 110592 B

__global__ void __launch_bounds__(256, 2) gemm_tf32(
    const float* __restrict__ A, const float* __restrict__ BT,
    const float* __restrict__ bias, float* __restrict__ C, int ncols)
{
    extern __shared__ float sm[];
    float* sA = sm;
    float* sB = sm + NST * STG;

    const int t = threadIdx.x;
    const int wid = t >> 5, lane = t & 31;
    const int wm = wid & 3, wn = wid >> 2;
    const int gid = lane >> 2, tig = lane & 3;
    const int n0 = blockIdx.x * BM;
    const int m0 = blockIdx.y * BM;
    const uint32_t sAu = smem_u32(sA);
    const uint32_t sBu = smem_u32(sB);

    auto loadAB = [&](int kc, int s) {
        #pragma unroll
        for (int i = 0; i < 4; i++) {
            int f = t + i * 256;
            int r = f >> 3, c4 = f & 7;
            cp_async16(sAu + (uint32_t)(s * STG + r * KP + c4 * 4) * 4,
                       A + (size_t)(m0 + r) * CDIM + kc * BK + c4 * 4);
        }
        #pragma unroll
        for (int i = 0; i < 4; i++) {
            int f = t + i * 256;
            int r = f >> 3, c4 = f & 7;
            cp_async16(sBu + (uint32_t)(s * STG + r * KP + c4 * 4) * 4,
                       BT + (size_t)(n0 + r) * CDIM + kc * BK + c4 * 4);
        }
    };

    float acc[2][8][4];
    #pragma unroll
    for (int mt = 0; mt < 2; mt++)
        #pragma unroll
        for (int nt = 0; nt < 8; nt++)
            #pragma unroll
            for (int e = 0; e < 4; e++) acc[mt][nt][e] = 0.0f;

    loadAB(0, 0); cp_commit();
    loadAB(1, 1); cp_commit();

    #pragma unroll 1
    for (int kc = 0; kc < CDIM / BK; kc++) {
        if (kc < CDIM / BK - 1) cp_wait<1>(); else cp_wait<0>();
        __syncthreads();

        const float* a_s = sA + (kc % NST) * STG;
        const float* b_s = sB + (kc % NST) * STG;
        #pragma unroll
        for (int kk = 0; kk < BK; kk += 8) {
            uint32_t af[2][4], bf[8][2];
            #pragma unroll
            for (int mt = 0; mt < 2; mt++) {
                const float* ap = a_s + (wm * 32 + mt * 16 + gid) * KP + kk + tig;
                af[mt][0] = __float_as_uint(ap[0]);
                af[mt][1] = __float_as_uint(ap[8 * KP]);
                af[mt][2] = __float_as_uint(ap[4]);
                af[mt][3] = __float_as_uint(ap[8 * KP + 4]);
            }
            #pragma unroll
            for (int nt = 0; nt < 8; nt++) {
                const float* bp = b_s + (wn * 64 + nt * 8 + gid) * KP + kk + tig;
                bf[nt][0] = __float_as_uint(bp[0]);
                bf[nt][1] = __float_as_uint(bp[4]);
            }
            #pragma unroll
            for (int mt = 0; mt < 2; mt++)
                #pragma unroll
                for (int nt = 0; nt < 8; nt++)
                    mma_tf32(acc[mt][nt], af[mt], bf[nt]);
        }
        if (kc + 2 < CDIM / BK) { loadAB(kc + 2, (kc + 2) % NST); cp_commit(); }
    }

    #pragma unroll
    for (int mt = 0; mt < 2; mt++) {
        const int r = m0 + wm * 32 + mt * 16 + gid;
        #pragma unroll
        for (int nt = 0; nt < 8; nt++) {
            const int c = n0 + wn * 64 + nt * 8 + tig * 2;
            float b0 = __ldg(bias + c), b1 = __ldg(bias + c + 1);
            float2 v0 = make_float2(acc[mt][nt][0] + b0, acc[mt][nt][1] + b1);
            float2 v1 = make_float2(acc[mt][nt][2] + b0, acc[mt][nt][3] + b1);
            *(float2*)(C + (size_t)r * ncols + c)       = v0;
            *(float2*)(C + (size_t)(r + 8) * ncols + c) = v1;
        }
    }
}

// ---------------------------------------------------------------------------
// Kernel k2: tensor-core attention (R10-proven version).
// ---------------------------------------------------------------------------
#define QP 36
#define PP 68
#define OFF_Q(wg)   ((wg) * 2304)
#define OFF_K(wg)   (4608 + (wg) * 2304)
#define OFF_V(wg)   (9216 + (wg) * 2304)
#define OFF_P(wg)   (13824 + (wg) * 4352)
#define WATTN_SMEM  ((13824 + 2 * 4352) * 4)   // 90112 B -> 2 CTAs/SM

__global__ void __launch_bounds__(256, 2) wattn(
    const float* __restrict__ qkv, const float4* __restrict__ bmt,
    float* __restrict__ O)
{
    extern __shared__ float sm[];
    const int t = threadIdx.x, wid = t >> 5, lane = t & 31;
    const int wg = wid >> 2, wm = wid & 3;
    const int gid = lane >> 2, tig = lane & 3;
    const int tt = t & 127;
    const int b = blockIdx.x;             // chunk-local window; chunk is mult of 64
    const int barid = 1 + wg;

    float* sQ = sm + OFF_Q(wg);
    float* sK = sm + OFF_K(wg);
    float* sV = sm + OFF_V(wg);
    float* sP = sm + OFF_P(wg);

    const float* base = qkv + (size_t)b * (64 * 768);
    float* og = O + (size_t)b * (64 * 256);

    // Prefetch head hp=0 Q/K into registers.
    float4 pq[4], pk[4];
    #pragma unroll
    for (int i = 0; i < 4; i++) {
        int u = tt + i * 128;
        int n = u >> 3, q = u & 7;
        const float4* rp = (const float4*)(base + n * 768 + wg * 32) + q;
        pq[i] = rp[0];
        pk[i] = rp[64];
    }

    const int r0 = wm * 16 + gid, r1 = r0 + 8;

    for (int hp = 0; hp < 4; hp++) {
        const int h = hp * 2 + wg;
        asm volatile("bar.sync %0, 128;" :: "r"(barid) : "memory");  // prev head reads done

        #pragma unroll
        for (int i = 0; i < 4; i++) {
            int u = tt + i * 128;
            int n = u >> 3, q = u & 7;
            float4 qa = pq[i];
            qa.x = tf32r(qa.x); qa.y = tf32r(qa.y); qa.z = tf32r(qa.z); qa.w = tf32r(qa.w);
            *(float4*)&sQ[n * QP + q * 4] = qa;
            float4 ka = pk[i];
            ka.x = tf32r(ka.x); ka.y = tf32r(ka.y); ka.z = tf32r(ka.z); ka.w = tf32r(ka.w);
            *(float4*)&sK[n * QP + q * 4] = ka;
            float4 va = *((const float4*)(base + n * 768 + h * 32) + q + 128);
            va.x = tf32r(va.x); va.y = tf32r(va.y); va.z = tf32r(va.z); va.w = tf32r(va.w);
            *(float4*)&sV[n * QP + q * 4] = va;
        }
        asm volatile("bar.sync %0, 128;" :: "r"(barid) : "memory");  // staging visible

        float4 bm[8];
        {
            const float4* bmp = bmt + (size_t)((h << 6) | (b & 63)) * 1024
                              + wm * 256 + gid * 4 + tig;
            #pragma unroll
            for (int nt = 0; nt < 8; nt++) bm[nt] = __ldg(bmp + nt * 32);
        }

        if (hp < 3) {
            #pragma unroll
            for (int i = 0; i < 4; i++) {
                int u = tt + i * 128;
                int n = u >> 3, q = u & 7;
                const float4* rp = (const float4*)(base + n * 768 + (h + 2) * 32) + q;
                pq[i] = rp[0];
                pk[i] = rp[64];
            }
        }

        float sacc[8][4];
        #pragma unroll
        for (int nt = 0; nt < 8; nt++)
            #pragma unroll
            for (int e = 0; e < 4; e++) sacc[nt][e] = 0.0f;
        #pragma unroll
        for (int kt = 0; kt < 4; kt++) {
            uint32_t af[4];
            const float* ap = sQ + r0 * QP + kt * 8 + tig;
            af[0] = __float_as_uint(ap[0]);
            af[1] = __float_as_uint(ap[8 * QP]);
            af[2] = __float_as_uint(ap[4]);
            af[3] = __float_as_uint(ap[8 * QP + 4]);
            #pragma unroll
            for (int nt = 0; nt < 8; nt++) {
                uint32_t bf[2];
                const float* bp = sK + (nt * 8 + gid) * QP + kt * 8 + tig;
                bf[0] = __float_as_uint(bp[0]);
                bf[1] = __float_as_uint(bp[4]);
                mma_tf32(sacc[nt], af, bf);
            }
        }

        float v0[16], v1[16];
        #pragma unroll
        for (int nt = 0; nt < 8; nt++) {
            v0[nt * 2 + 0] = fmaf(sacc[nt][0], SCALEF, bm[nt].x);
            v0[nt * 2 + 1] = fmaf(sacc[nt][1], SCALEF, bm[nt].y);
            v1[nt * 2 + 0] = fmaf(sacc[nt][2], SCALEF, bm[nt].z);
            v1[nt * 2 + 1] = fmaf(sacc[nt][3], SCALEF, bm[nt].w);
        }
        float mx0 = -1e30f, mx1 = -1e30f;
        #pragma unroll
        for (int i = 0; i < 16; i++) { mx0 = fmaxf(mx0, v0[i]); mx1 = fmaxf(mx1, v1[i]); }
        mx0 = fmaxf(mx0, __shfl_xor_sync(0xffffffffu, mx0, 1));
        mx0 = fmaxf(mx0, __shfl_xor_sync(0xffffffffu, mx0, 2));
        mx1 = fmaxf(mx1, __shfl_xor_sync(0xffffffffu, mx1, 1));
        mx1 = fmaxf(mx1, __shfl_xor_sync(0xffffffffu, mx1, 2));
        float s0 = 0.0f, s1 = 0.0f;
        #pragma unroll
        for (int i = 0; i < 16; i++) {
            v0[i] = __expf(v0[i] - mx0); s0 += v0[i];
            v1[i] = __expf(v1[i] - mx1); s1 += v1[i];
        }
        s0 += __shfl_xor_sync(0xffffffffu, s0, 1);
        s0 += __shfl_xor_sync(0xffffffffu, s0, 2);
        s1 += __shfl_xor_sync(0xffffffffu, s1, 1);
        s1 += __shfl_xor_sync(0xffffffffu, s1, 2);
        const float i0 = 1.0f / s0, i1 = 1.0f / s1;
        #pragma unroll
        for (int nt = 0; nt < 8; nt++) {
            int c = nt * 8 + tig * 2;
            float2 p0 = make_float2(tf32r(v0[nt * 2] * i0), tf32r(v0[nt * 2 + 1] * i0));
            float2 p1 = make_float2(tf32r(v1[nt * 2] * i1), tf32r(v1[nt * 2 + 1] * i1));
            *(float2*)&sP[r0 * PP + c] = p0;
            *(float2*)&sP[r1 * PP + c] = p1;
        }
        __syncwarp();   // P rows read back are warp-private

        float oacc[4][4];
        #pragma unroll
        for (int nt = 0; nt < 4; nt++)
            #pragma unroll
            for (int e = 0; e < 4; e++) oacc[nt][e] = 0.0f;
        #pragma unroll
        for (int kt = 0; kt < 8; kt++) {
            uint32_t af[4];
            const float* pp = sP + r0 * PP + kt * 8 + tig;
            af[0] = __float_as_uint(pp[0]);
            af[1] = __float_as_uint(pp[8 * PP]);
            af[2] = __float_as_uint(pp[4]);
            af[3] = __float_as_uint(pp[8 * PP + 4]);
            #pragma unroll
            for (int nt = 0; nt < 4; nt++) {
                uint32_t bf[2];
                const float* vp = sV + (kt * 8 + tig) * QP + nt * 8 + gid;
                bf[0] = __float_as_uint(vp[0]);
                bf[1] = __float_as_uint(vp[4 * QP]);
                mma_tf32(oacc[nt], af, bf);
            }
        }
        #pragma unroll
        for (int nt = 0; nt < 4; nt++) {
            const int c = h * 32 + nt * 8 + tig * 2;
            *(float2*)&og[r0 * 256 + c] =
                make_float2(tf32r(oacc[nt][0]), tf32r(oacc[nt][1]));
            *(float2*)&og[r1 * 256 + c] =
                make_float2(tf32r(oacc[nt][2]), tf32r(oacc[nt][3]));
        }
    }
}

// ---------------------------------------------------------------------------
extern "C" void kernel_launch(void* const* d_in, const int* in_sizes, int n_in,
                              void* d_out, int out_size)
{
    const float* x          = (const float*)d_in[0];
    const float* mask       = (const float*)d_in[1];
    const float* wqkv       = (const float*)d_in[2];
    const float* bqkv       = (const float*)d_in[3];
    const float* wproj      = (const float*)d_in[4];
    const float* bproj      = (const float*)d_in[5];
    const float* bias_table = (const float*)d_in[6];
    (void)in_sizes; (void)n_in; (void)out_size;

    cudaFuncSetAttribute(gemm_tf32, cudaFuncAttributeMaxDynamicSharedMemorySize, GEMM_SMEM);
    cudaFuncSetAttribute(wattn, cudaFuncAttributeMaxDynamicSharedMemorySize, WATTN_SMEM);

    float *qkvT, *projT, *qkvS, *oS, *xr;
    float4* bmT;
    cudaGetSymbolAddress((void**)&qkvT,  g_WqkvT);
    cudaGetSymbolAddress((void**)&projT, g_WprojT);
    cudaGetSymbolAddress((void**)&qkvS,  g_QKV);
    cudaGetSymbolAddress((void**)&oS,    g_O);
    cudaGetSymbolAddress((void**)&xr,    g_Xr);
    cudaGetSymbolAddress((void**)&bmT,   g_BM);

    // Side stream + events for the chunk pipeline (host-side objects only;
    // kernel_launch is invoked a handful of times, so per-call creation is fine).
    cudaStream_t s1;
    cudaStreamCreateWithFlags(&s1, cudaStreamNonBlocking);
    cudaEvent_t evQKV[NCHUNK], evATT[NCHUNK];
    for (int c = 0; c < NCHUNK; c++) {
        cudaEventCreateWithFlags(&evQKV[c], cudaEventDisableTiming);
        cudaEventCreateWithFlags(&evATT[c], cudaEventDisableTiming);
    }

    // Prep on the main (captured) stream.
    round_tf32<<<65536, 256>>>((const float4*)x, (float4*)xr);
    transpose_tf32<<<dim3(24, 8), dim3(32, 8)>>>(wqkv,  qkvT, 768);
    transpose_tf32<<<dim3(8, 8),  dim3(32, 8)>>>(wproj, projT, 256);
    bm_build<<<512, 256>>>(mask, bias_table, bmT);

    const size_t xOff = (size_t)WCH * 64 * 256;   // floats per chunk of x / O / out
    const size_t qOff = (size_t)WCH * 64 * 768;   // floats per chunk of QKV

    // k1 chunks on main stream, fence each with an event.
    for (int c = 0; c < NCHUNK; c++) {
        gemm_tf32<<<dim3(6, MCH), 256, GEMM_SMEM>>>(
            xr + (size_t)c * xOff, qkvT, bqkv, qkvS + (size_t)c * qOff, 768);
        cudaEventRecord(evQKV[c], 0);
    }
    // k2 chunks on side stream, each gated on its k1 chunk.
    for (int c = 0; c < NCHUNK; c++) {
        cudaStreamWaitEvent(s1, evQKV[c], 0);
        wattn<<<WCH, 256, WATTN_SMEM, s1>>>(
            qkvS + (size_t)c * qOff, bmT, oS + (size_t)c * xOff);
        cudaEventRecord(evATT[c], s1);
    }
    // k3 chunks back on main stream, each gated on its k2 chunk (joins s1).
    for (int c = 0; c < NCHUNK; c++) {
        cudaStreamWaitEvent(0, evATT[c], 0);
        gemm_tf32<<<dim3(2, MCH), 256, GEMM_SMEM>>>(
            oS + (size_t)c * xOff, projT, bproj,
            (float*)d_out + (size_t)c * xOff, 256);
    }
}

// round 16
// speedup vs baseline: 1.1057x; 1.1057x over previous
#include <cuda_runtime.h>
#include <cstdint>

// Window attention: B_=4096 windows, N=64 tok, C=256, H=8 heads, D=32. fp32 I/O.
// R10-proven structure, serial launches. NEW vs R10: round_tf32 pass deleted;
// k1 loads raw x via cp.async and tf32-rounds the A FRAGMENTS in-register
// (8 CVT per k-step vs 16 MMA; issue headroom measured at 26%).
//   t0: transpose+round w_qkv/w_proj -> g_W*T (tf32)
//   b0: g_BM[h][w] = bias+mask in MMA-fragment order
//   k1: gemm<CVTA=1>  g_QKV = x @ WqkvT^T + b_qkv
//   k2: mma.sync tf32 attention -> g_O (written tf32-rounded)
//   k3: gemm<CVTA=0>  out = g_O @ WprojT^T + b_proj
// (PTX target compute_103: tcgen05 unavailable; legacy mma.sync tf32 path.)

#define NWIN   4096
#define CDIM   256
#define NHEAD  8
#define SCALEF 0.17677669529663687f

__device__ float  g_QKV[(size_t)NWIN * 64 * 768];
__device__ float  g_O  [(size_t)NWIN * 64 * 256];
__device__ float  g_WqkvT [768 * 256];
__device__ float  g_WprojT[256 * 256];
__device__ float4 g_BM[8 * 64 * 1024];      // 8 MB: [h][w][wm][nt][gid][tig]

__device__ __forceinline__ float tf32r(float x) {
    float y; asm("cvt.rna.tf32.f32 %0, %1;" : "=f"(y) : "f"(x)); return y;
}
__device__ __forceinline__ uint32_t smem_u32(const void* p) {
    uint32_t a;
    asm("{ .reg .u64 t; cvta.to.shared.u64 t, %1; cvt.u32.u64 %0, t; }" : "=r"(a) : "l"(p));
    return a;
}
__device__ __forceinline__ void cp_async16(uint32_t dst, const void* src) {
    asm volatile("cp.async.cg.shared.global [%0], [%1], 16;" :: "r"(dst), "l"(src));
}
__device__ __forceinline__ void cp_commit() {
    asm volatile("cp.async.commit_group;" ::: "memory");
}
template<int N> __device__ __forceinline__ void cp_wait() {
    asm volatile("cp.async.wait_group %0;" :: "n"(N) : "memory");
}

// m16n8k8 tf32 mma: D += A(16x8,row) * B(8x8,col).
__device__ __forceinline__ void mma_tf32(float* d, const uint32_t* a, const uint32_t* b) {
    asm volatile(
        "mma.sync.aligned.m16n8k8.row.col.f32.tf32.tf32.f32 "
        "{%0,%1,%2,%3}, {%4,%5,%6,%7}, {%8,%9}, {%0,%1,%2,%3};"
        : "+f"(d[0]), "+f"(d[1]), "+f"(d[2]), "+f"(d[3])
        : "r"(a[0]), "r"(a[1]), "r"(a[2]), "r"(a[3]), "r"(b[0]), "r"(b[1]));
}

// ---------------------------------------------------------------------------
// Kernel t0: transpose src[256, ncol] -> dst[ncol, 256], tf32-rounded.
// ---------------------------------------------------------------------------
__global__ void transpose_tf32(const float* __restrict__ src, float* __restrict__ dst, int ncol)
{
    __shared__ float tile[32][33];
    const int bx = blockIdx.x, by = blockIdx.y;
    const int tx = threadIdx.x, ty0 = threadIdx.y;
    #pragma unroll
    for (int j = 0; j < 32; j += 8)
        tile[ty0 + j][tx] = src[(size_t)(by * 32 + ty0 + j) * ncol + bx * 32 + tx];
    __syncthreads();
    #pragma unroll
    for (int j = 0; j < 32; j += 8)
        dst[(size_t)(bx * 32 + ty0 + j) * 256 + by * 32 + tx] = tf32r(tile[tx][ty0 + j]);
}

// ---------------------------------------------------------------------------
// Kernel b0: build bias+mask fragment table.
// ---------------------------------------------------------------------------
__global__ void bm_build(const float* __restrict__ mask, const float* __restrict__ bt,
                         float4* __restrict__ out)
{
    const int hw = blockIdx.x;             // 0..511
    const int h = hw >> 6, w = hw & 63;
    const int t = threadIdx.x;             // 256
    const int nt = t >> 5, gid = (t >> 2) & 7, tig = t & 3;
    const float* mrow = mask + (size_t)w * 4096;
    float4* op = out + (size_t)hw * 1024 + nt * 32 + gid * 4 + tig;
    const int c = nt * 8 + tig * 2;
    #pragma unroll
    for (int wm = 0; wm < 4; wm++) {
        const int r0 = wm * 16 + gid, r1 = r0 + 8;
        float4 v;
        v.x = bt[(r0 - c + 63) * 8 + h] + mrow[r0 * 64 + c];
        v.y = bt[(r0 - c + 62) * 8 + h] + mrow[r0 * 64 + c + 1];
        v.z = bt[(r1 - c + 63) * 8 + h] + mrow[r1 * 64 + c];
        v.w = bt[(r1 - c + 62) * 8 + h] + mrow[r1 * 64 + c + 1];
        op[wm * 256] = v;
    }
}

// ---------------------------------------------------------------------------
// Kernel k1/k3: 3-stage cp.async mma.sync tf32 GEMM (R10-proven pipeline).
// CVTA=1: A is raw fp32 (x); fragments tf32-rounded in-register after LDS.
// CVTA=0: A already tf32 (g_O from wattn).  BT always pre-rounded.
// ---------------------------------------------------------------------------
#define BM 128
#define BK 32
#define KP 36
#define STG (BM * KP)
#define NST 3
#define GEMM_SMEM (2 * NST * STG * 4)       // 110592 B

template<int CVTA>
__global__ void __launch_bounds__(256, 2) gemm_tf32(
    const float* __restrict__ A, const float* __restrict__ BT,
    const float* __restrict__ bias, float* __restrict__ C, int ncols)
{
    extern __shared__ float sm[];
    float* sA = sm;
    float* sB = sm + NST * STG;

    const int t = threadIdx.x;
    const int wid = t >> 5, lane = t & 31;
    const int wm = wid & 3, wn = wid >> 2;
    const int gid = lane >> 2, tig = lane & 3;
    const int n0 = blockIdx.x * BM;
    const int m0 = blockIdx.y * BM;
    const uint32_t sAu = smem_u32(sA);
    const uint32_t sBu = smem_u32(sB);

    auto loadAB = [&](int kc, int s) {
        #pragma unroll
        for (int i = 0; i < 4; i++) {
            int f = t + i * 256;
            int r = f >> 3, c4 = f & 7;
            cp_async16(sAu + (uint32_t)(s * STG + r * KP + c4 * 4) * 4,
                       A + (size_t)(m0 + r) * CDIM + kc * BK + c4 * 4);
        }
        #pragma unroll
        for (int i = 0; i < 4; i++) {
            int f = t + i * 256;
            int r = f >> 3, c4 = f & 7;
            cp_async16(sBu + (uint32_t)(s * STG + r * KP + c4 * 4) * 4,
                       BT + (size_t)(n0 + r) * CDIM + kc * BK + c4 * 4);
        }
    };

    float acc[2][8][4];
    #pragma unroll
    for (int mt = 0; mt < 2; mt++)
        #pragma unroll
        for (int nt = 0; nt < 8; nt++)
            #pragma unroll
            for (int e = 0; e < 4; e++) acc[mt][nt][e] = 0.0f;

    loadAB(0, 0); cp_commit();
    loadAB(1, 1); cp_commit();

    #pragma unroll 1
    for (int kc = 0; kc < CDIM / BK; kc++) {
        if (kc < CDIM / BK - 1) cp_wait<1>(); else cp_wait<0>();
        __syncthreads();

        const float* a_s = sA + (kc % NST) * STG;
        const float* b_s = sB + (kc % NST) * STG;
        #pragma unroll
        for (int kk = 0; kk < BK; kk += 8) {
            uint32_t af[2][4], bf[8][2];
            #pragma unroll
            for (int mt = 0; mt < 2; mt++) {
                const float* ap = a_s + (wm * 32 + mt * 16 + gid) * KP + kk + tig;
                float a0 = ap[0], a1 = ap[8 * KP], a2 = ap[4], a3 = ap[8 * KP + 4];
                if (CVTA) { a0 = tf32r(a0); a1 = tf32r(a1); a2 = tf32r(a2); a3 = tf32r(a3); }
                af[mt][0] = __float_as_uint(a0);
                af[mt][1] = __float_as_uint(a1);
                af[mt][2] = __float_as_uint(a2);
                af[mt][3] = __float_as_uint(a3);
            }
            #pragma unroll
            for (int nt = 0; nt < 8; nt++) {
                const float* bp = b_s + (wn * 64 + nt * 8 + gid) * KP + kk + tig;
                bf[nt][0] = __float_as_uint(bp[0]);
                bf[nt][1] = __float_as_uint(bp[4]);
            }
            #pragma unroll
            for (int mt = 0; mt < 2; mt++)
                #pragma unroll
                for (int nt = 0; nt < 8; nt++)
                    mma_tf32(acc[mt][nt], af[mt], bf[nt]);
        }
        if (kc + 2 < CDIM / BK) { loadAB(kc + 2, (kc + 2) % NST); cp_commit(); }
    }

    #pragma unroll
    for (int mt = 0; mt < 2; mt++) {
        const int r = m0 + wm * 32 + mt * 16 + gid;
        #pragma unroll
        for (int nt = 0; nt < 8; nt++) {
            const int c = n0 + wn * 64 + nt * 8 + tig * 2;
            float b0 = __ldg(bias + c), b1 = __ldg(bias + c + 1);
            float2 v0 = make_float2(acc[mt][nt][0] + b0, acc[mt][nt][1] + b1);
            float2 v1 = make_float2(acc[mt][nt][2] + b0, acc[mt][nt][3] + b1);
            *(float2*)(C + (size_t)r * ncols + c)       = v0;
            *(float2*)(C + (size_t)(r + 8) * ncols + c) = v1;
        }
    }
}

// ---------------------------------------------------------------------------
// Kernel k2: tensor-core attention (R10-proven version).
// ---------------------------------------------------------------------------
#define QP 36
#define PP 68
#define OFF_Q(wg)   ((wg) * 2304)
#define OFF_K(wg)   (4608 + (wg) * 2304)
#define OFF_V(wg)   (9216 + (wg) * 2304)
#define OFF_P(wg)   (13824 + (wg) * 4352)
#define WATTN_SMEM  ((13824 + 2 * 4352) * 4)   // 90112 B -> 2 CTAs/SM

__global__ void __launch_bounds__(256, 2) wattn(
    const float* __restrict__ qkv, const float4* __restrict__ bmt,
    float* __restrict__ O)
{
    extern __shared__ float sm[];
    const int t = threadIdx.x, wid = t >> 5, lane = t & 31;
    const int wg = wid >> 2, wm = wid & 3;
    const int gid = lane >> 2, tig = lane & 3;
    const int tt = t & 127;
    const int b = blockIdx.x;
    const int barid = 1 + wg;

    float* sQ = sm + OFF_Q(wg);
    float* sK = sm + OFF_K(wg);
    float* sV = sm + OFF_V(wg);
    float* sP = sm + OFF_P(wg);

    const float* base = qkv + (size_t)b * (64 * 768);
    float* og = O + (size_t)b * (64 * 256);

    // Prefetch head hp=0 Q/K into registers.
    float4 pq[4], pk[4];
    #pragma unroll
    for (int i = 0; i < 4; i++) {
        int u = tt + i * 128;
        int n = u >> 3, q = u & 7;
        const float4* rp = (const float4*)(base + n * 768 + wg * 32) + q;
        pq[i] = rp[0];
        pk[i] = rp[64];
    }

    const int r0 = wm * 16 + gid, r1 = r0 + 8;

    for (int hp = 0; hp < 4; hp++) {
        const int h = hp * 2 + wg;
        asm volatile("bar.sync %0, 128;" :: "r"(barid) : "memory");  // prev head reads done

        #pragma unroll
        for (int i = 0; i < 4; i++) {
            int u = tt + i * 128;
            int n = u >> 3, q = u & 7;
            float4 qa = pq[i];
            qa.x = tf32r(qa.x); qa.y = tf32r(qa.y); qa.z = tf32r(qa.z); qa.w = tf32r(qa.w);
            *(float4*)&sQ[n * QP + q * 4] = qa;
            float4 ka = pk[i];
            ka.x = tf32r(ka.x); ka.y = tf32r(ka.y); ka.z = tf32r(ka.z); ka.w = tf32r(ka.w);
            *(float4*)&sK[n * QP + q * 4] = ka;
            float4 va = *((const float4*)(base + n * 768 + h * 32) + q + 128);
            va.x = tf32r(va.x); va.y = tf32r(va.y); va.z = tf32r(va.z); va.w = tf32r(va.w);
            *(float4*)&sV[n * QP + q * 4] = va;
        }
        asm volatile("bar.sync %0, 128;" :: "r"(barid) : "memory");  // staging visible

        float4 bm[8];
        {
            const float4* bmp = bmt + (size_t)((h << 6) | (b & 63)) * 1024
                              + wm * 256 + gid * 4 + tig;
            #pragma unroll
            for (int nt = 0; nt < 8; nt++) bm[nt] = __ldg(bmp + nt * 32);
        }

        if (hp < 3) {
            #pragma unroll
            for (int i = 0; i < 4; i++) {
                int u = tt + i * 128;
                int n = u >> 3, q = u & 7;
                const float4* rp = (const float4*)(base + n * 768 + (h + 2) * 32) + q;
                pq[i] = rp[0];
                pk[i] = rp[64];
            }
        }

        float sacc[8][4];
        #pragma unroll
        for (int nt = 0; nt < 8; nt++)
            #pragma unroll
            for (int e = 0; e < 4; e++) sacc[nt][e] = 0.0f;
        #pragma unroll
        for (int kt = 0; kt < 4; kt++) {
            uint32_t af[4];
            const float* ap = sQ + r0 * QP + kt * 8 + tig;
            af[0] = __float_as_uint(ap[0]);
            af[1] = __float_as_uint(ap[8 * QP]);
            af[2] = __float_as_uint(ap[4]);
            af[3] = __float_as_uint(ap[8 * QP + 4]);
            #pragma unroll
            for (int nt = 0; nt < 8; nt++) {
                uint32_t bf[2];
                const float* bp = sK + (nt * 8 + gid) * QP + kt * 8 + tig;
                bf[0] = __float_as_uint(bp[0]);
                bf[1] = __float_as_uint(bp[4]);
                mma_tf32(sacc[nt], af, bf);
            }
        }

        float v0[16], v1[16];
        #pragma unroll
        for (int nt = 0; nt < 8; nt++) {
            v0[nt * 2 + 0] = fmaf(sacc[nt][0], SCALEF, bm[nt].x);
            v0[nt * 2 + 1] = fmaf(sacc[nt][1], SCALEF, bm[nt].y);
            v1[nt * 2 + 0] = fmaf(sacc[nt][2], SCALEF, bm[nt].z);
            v1[nt * 2 + 1] = fmaf(sacc[nt][3], SCALEF, bm[nt].w);
        }
        float mx0 = -1e30f, mx1 = -1e30f;
        #pragma unroll
        for (int i = 0; i < 16; i++) { mx0 = fmaxf(mx0, v0[i]); mx1 = fmaxf(mx1, v1[i]); }
        mx0 = fmaxf(mx0, __shfl_xor_sync(0xffffffffu, mx0, 1));
        mx0 = fmaxf(mx0, __shfl_xor_sync(0xffffffffu, mx0, 2));
        mx1 = fmaxf(mx1, __shfl_xor_sync(0xffffffffu, mx1, 1));
        mx1 = fmaxf(mx1, __shfl_xor_sync(0xffffffffu, mx1, 2));
        float s0 = 0.0f, s1 = 0.0f;
        #pragma unroll
        for (int i = 0; i < 16; i++) {
            v0[i] = __expf(v0[i] - mx0); s0 += v0[i];
            v1[i] = __expf(v1[i] - mx1); s1 += v1[i];
        }
        s0 += __shfl_xor_sync(0xffffffffu, s0, 1);
        s0 += __shfl_xor_sync(0xffffffffu, s0, 2);
        s1 += __shfl_xor_sync(0xffffffffu, s1, 1);
        s1 += __shfl_xor_sync(0xffffffffu, s1, 2);
        const float i0 = 1.0f / s0, i1 = 1.0f / s1;
        #pragma unroll
        for (int nt = 0; nt < 8; nt++) {
            int c = nt * 8 + tig * 2;
            float2 p0 = make_float2(tf32r(v0[nt * 2] * i0), tf32r(v0[nt * 2 + 1] * i0));
            float2 p1 = make_float2(tf32r(v1[nt * 2] * i1), tf32r(v1[nt * 2 + 1] * i1));
            *(float2*)&sP[r0 * PP + c] = p0;
            *(float2*)&sP[r1 * PP + c] = p1;
        }
        __syncwarp();   // P rows read back are warp-private

        float oacc[4][4];
        #pragma unroll
        for (int nt = 0; nt < 4; nt++)
            #pragma unroll
            for (int e = 0; e < 4; e++) oacc[nt][e] = 0.0f;
        #pragma unroll
        for (int kt = 0; kt < 8; kt++) {
            uint32_t af[4];
            const float* pp = sP + r0 * PP + kt * 8 + tig;
            af[0] = __float_as_uint(pp[0]);
            af[1] = __float_as_uint(pp[8 * PP]);
            af[2] = __float_as_uint(pp[4]);
            af[3] = __float_as_uint(pp[8 * PP + 4]);
            #pragma unroll
            for (int nt = 0; nt < 4; nt++) {
                uint32_t bf[2];
                const float* vp = sV + (kt * 8 + tig) * QP + nt * 8 + gid;
                bf[0] = __float_as_uint(vp[0]);
                bf[1] = __float_as_uint(vp[4 * QP]);
                mma_tf32(oacc[nt], af, bf);
            }
        }
        #pragma unroll
        for (int nt = 0; nt < 4; nt++) {
            const int c = h * 32 + nt * 8 + tig * 2;
            *(float2*)&og[r0 * 256 + c] =
                make_float2(tf32r(oacc[nt][0]), tf32r(oacc[nt][1]));
            *(float2*)&og[r1 * 256 + c] =
                make_float2(tf32r(oacc[nt][2]), tf32r(oacc[nt][3]));
        }
    }
}

// ---------------------------------------------------------------------------
extern "C" void kernel_launch(void* const* d_in, const int* in_sizes, int n_in,
                              void* d_out, int out_size)
{
    const float* x          = (const float*)d_in[0];
    const float* mask       = (const float*)d_in[1];
    const float* wqkv       = (const float*)d_in[2];
    const float* bqkv       = (const float*)d_in[3];
    const float* wproj      = (const float*)d_in[4];
    const float* bproj      = (const float*)d_in[5];
    const float* bias_table = (const float*)d_in[6];
    (void)in_sizes; (void)n_in; (void)out_size;

    cudaFuncSetAttribute(gemm_tf32<1>, cudaFuncAttributeMaxDynamicSharedMemorySize, GEMM_SMEM);
    cudaFuncSetAttribute(gemm_tf32<0>, cudaFuncAttributeMaxDynamicSharedMemorySize, GEMM_SMEM);
    cudaFuncSetAttribute(wattn, cudaFuncAttributeMaxDynamicSharedMemorySize, WATTN_SMEM);

    float *qkvT, *projT, *qkvS, *oS;
    float4* bmT;
    cudaGetSymbolAddress((void**)&qkvT,  g_WqkvT);
    cudaGetSymbolAddress((void**)&projT, g_WprojT);
    cudaGetSymbolAddress((void**)&qkvS,  g_QKV);
    cudaGetSymbolAddress((void**)&oS,    g_O);
    cudaGetSymbolAddress((void**)&bmT,   g_BM);

    transpose_tf32<<<dim3(24, 8), dim3(32, 8)>>>(wqkv,  qkvT, 768);
    transpose_tf32<<<dim3(8, 8),  dim3(32, 8)>>>(wproj, projT, 256);
    bm_build<<<512, 256>>>(mask, bias_table, bmT);
    gemm_tf32<1><<<dim3(6, 2048), 256, GEMM_SMEM>>>(x, qkvT, bqkv, qkvS, 768);
    wattn<<<NWIN, 256, WATTN_SMEM>>>(qkvS, bmT, oS);
    gemm_tf32<0><<<dim3(2, 2048), 256, GEMM_SMEM>>>(oS, projT, bproj, (float*)d_out, 256);
}